// round 4
// baseline (speedup 1.0000x reference)
#include <cuda_runtime.h>

namespace qc {

constexpr int NQ = 14;
constexpr int NL = 4;
constexpr int NS = 1 << NQ;       // 16384 amplitudes
constexpr int NT = 1024;          // 32 warps -> occ 50%, 1 group of 16 amps per thread
constexpr int NC = NQ - 1;
constexpr int NWARP = NT / 32;

// shared memory layout (float offsets)
constexpr int OFF_IM  = NS;
constexpr int OFF_U   = 2 * NS;                    // 56 gates * 8 floats
constexpr int OFF_EP  = OFF_U + NL * NQ * 8;       // 52 phases p
constexpr int OFF_EQ  = OFF_EP + NL * NC * 2;      // 52 phases q
constexpr int OFF_ENC = OFF_EQ + NL * NC * 2;      // 14 (c,s) pairs
constexpr int OFF_RED = OFF_ENC + 2 * NQ;
constexpr int SMEM_FLOATS = OFF_RED + NWARP * NQ;
constexpr int SMEM_BYTES  = SMEM_FLOATS * 4;

// XOR swizzle: conflict-free for all sweep bases used (S in {0,3,6,9,10})
__device__ __forceinline__ int swz(int i) { return i ^ ((i >> 4) & 31); }

// Fused sweep over bits S..S+W-1:
//   1q gates on local bits G0..W-1, then CNOT(S+st,S+st+1)+RZ for st=C0..W-2 (ascending).
// INIT: synthesize the RY-encoded product state instead of loading.
// With NT=1024 and W=4 each thread processes exactly one 16-amplitude group.
template<int S, int W, int G0, int C0, bool INIT>
__device__ __forceinline__ void sweepFused(float* __restrict__ re, float* __restrict__ im,
                                           const float* __restrict__ ul,  // 14*8 gate floats
                                           const float* __restrict__ pl,  // 13*2 phases
                                           const float* __restrict__ ql,
                                           const float* __restrict__ enc, // 14*2 (c,s)
                                           int tid) {
  constexpr int M = 1 << W;
  static_assert((NS >> W) == NT, "one group per thread");
  const int g = tid;
  const int base = ((g >> S) << (S + W)) | (g & ((1 << S) - 1));
  float vr[M], vi[M];

  if (INIT) {
    float T = 1.0f;
#pragma unroll
    for (int i = W; i < NQ; ++i)
      T *= ((base >> i) & 1) ? enc[2 * i + 1] : enc[2 * i];
#pragma unroll
    for (int o = 0; o < M; ++o) {
      float p = T;
#pragma unroll
      for (int i = 0; i < W; ++i)
        p *= ((o >> i) & 1) ? enc[2 * i + 1] : enc[2 * i];
      vr[o] = p; vi[o] = 0.0f;
    }
  } else {
#pragma unroll
    for (int o = 0; o < M; ++o) {
      const int p = swz(base | (o << S));
      vr[o] = re[p]; vi[o] = im[p];
    }
  }

  // 1q gates (distinct bits -> commuting); coefficients loaded per gate from SMEM
#pragma unroll
  for (int j = G0; j < W; ++j) {
    const float* u = ul + (S + j) * 8;
    const float u0 = u[0], u1 = u[1], u2 = u[2], u3 = u[3];
    const float u4 = u[4], u5 = u[5], u6 = u[6], u7 = u[7];
#pragma unroll
    for (int o = 0; o < M; ++o) {
      if (o & (1 << j)) continue;
      const int o1 = o | (1 << j);
      const float ar = vr[o], ai = vi[o], br = vr[o1], bi = vi[o1];
      vr[o]  = u0*ar - u1*ai + u2*br - u3*bi;
      vi[o]  = u0*ai + u1*ar + u2*bi + u3*br;
      vr[o1] = u4*ar - u5*ai + u6*br - u7*bi;
      vi[o1] = u4*ai + u5*ar + u6*bi + u7*br;
    }
  }

  // CNOT chain + RZ on target (ascending st = chain order)
#pragma unroll
  for (int st = C0; st < W - 1; ++st) {
    const int tb = st + 1;
    const float p0 = pl[(S + st) * 2], p1 = pl[(S + st) * 2 + 1];
    const float q0 = ql[(S + st) * 2], q1 = ql[(S + st) * 2 + 1];
#pragma unroll
    for (int o = 0; o < M; ++o) {
      if (o & (1 << tb)) continue;
      const int o1 = o | (1 << tb);
      const bool ctrl = (o >> st) & 1;
      float ar, ai, br, bi;
      if (ctrl) { ar = vr[o1]; ai = vi[o1]; br = vr[o];  bi = vi[o];  }
      else      { ar = vr[o];  ai = vi[o];  br = vr[o1]; bi = vi[o1]; }
      vr[o]  = p0*ar - p1*ai;
      vi[o]  = p0*ai + p1*ar;
      vr[o1] = q0*br - q1*bi;
      vi[o1] = q0*bi + q1*br;
    }
  }

#pragma unroll
  for (int o = 0; o < M; ++o) {
    const int p = swz(base | (o << S));
    re[p] = vr[o]; im[p] = vi[o];
  }
}

__global__ void __launch_bounds__(NT, 1)
qc_kernel(const float* __restrict__ x, const float* __restrict__ prx,
          const float* __restrict__ pry, const float* __restrict__ prz,
          const float* __restrict__ pent, float* __restrict__ out) {
  extern __shared__ float sm[];
  float* re = sm;
  float* im = sm + OFF_IM;
  const float* enc = sm + OFF_ENC;
  const int tid = threadIdx.x;
  const int b = blockIdx.x;

  // ---- prologue: fused U = Rz*Ry*Rx, entangle RZ phases, RY-encoding factors ----
  if (tid < NL * NQ) {
    float cx, sx, cy, sy, cz, sz;
    sincosf(0.5f * prx[tid], &sx, &cx);
    sincosf(0.5f * pry[tid], &sy, &cy);
    sincosf(0.5f * prz[tid], &sz, &cz);
    const float r00x =  cy*cx, r00y =  sy*sx;
    const float r01x = -sy*cx, r01y = -cy*sx;
    const float r10x =  sy*cx, r10y = -cy*sx;
    const float r11x =  cy*cx, r11y = -sy*sx;
    float* u = sm + OFF_U + tid * 8;
    u[0] = r00x*cz + r00y*sz;  u[1] = r00y*cz - r00x*sz;
    u[2] = r01x*cz + r01y*sz;  u[3] = r01y*cz - r01x*sz;
    u[4] = r10x*cz - r10y*sz;  u[5] = r10x*sz + r10y*cz;
    u[6] = r11x*cz - r11y*sz;  u[7] = r11x*sz + r11y*cz;
  }
  if (tid >= 64 && tid < 64 + NL * NC) {
    const int e = tid - 64;
    float c, s; sincosf(0.5f * pent[e], &s, &c);
    sm[OFF_EP + 2*e] = c; sm[OFF_EP + 2*e + 1] = -s;   // e^{-i t/2}
    sm[OFF_EQ + 2*e] = c; sm[OFF_EQ + 2*e + 1] =  s;   // e^{+i t/2}
  }
  if (tid >= 128 && tid < 128 + NQ) {
    const int i = tid - 128;
    const float th = 0.5f * 3.14159265358979323846f * tanhf(x[b * NQ + i]);
    float c, s; sincosf(th, &s, &c);
    sm[OFF_ENC + 2*i] = c; sm[OFF_ENC + 2*i + 1] = s;
  }
  __syncthreads();

  // ---- layers: 5 fused sweeps; layer-0 sweep-1 synthesizes the init state ----
  for (int l = 0; l < NL; ++l) {
    const float* ul = sm + OFF_U  + l * NQ * 8;
    const float* pl = sm + OFF_EP + l * NC * 2;
    const float* ql = sm + OFF_EQ + l * NC * 2;
    if (l == 0) {
      sweepFused<0, 4, 0, 0, true >(re, im, ul, pl, ql, enc, tid);
    } else {
      __syncthreads();
      sweepFused<0, 4, 0, 0, false>(re, im, ul, pl, ql, enc, tid);
    }
    __syncthreads(); sweepFused<3,  4, 1, 0, false>(re, im, ul, pl, ql, enc, tid);
    __syncthreads(); sweepFused<6,  4, 1, 0, false>(re, im, ul, pl, ql, enc, tid);
    __syncthreads(); sweepFused<9,  4, 1, 0, false>(re, im, ul, pl, ql, enc, tid);
    __syncthreads(); sweepFused<10, 4, 3, 2, false>(re, im, ul, pl, ql, enc, tid);
  }
  __syncthreads();

  // ---- measurement: <Z_q> = sum prob * (1 - 2*bit_q) ----
  float acc[NQ];
#pragma unroll
  for (int q = 0; q < NQ; ++q) acc[q] = 0.0f;
#pragma unroll
  for (int k = 0; k < NS / NT; ++k) {
    const int idx = tid + k * NT;
    const int p = swz(idx);
    const float rr = re[p], ii = im[p];
    const float pr = rr * rr + ii * ii;
#pragma unroll
    for (int q = 0; q < NQ; ++q) {
      if (idx & (1 << q)) acc[q] -= pr; else acc[q] += pr;
    }
  }
#pragma unroll
  for (int q = 0; q < NQ; ++q)
#pragma unroll
    for (int off = 16; off > 0; off >>= 1)
      acc[q] += __shfl_xor_sync(0xffffffffu, acc[q], off);
  const int warp = tid >> 5, lane = tid & 31;
  if (lane == 0) {
#pragma unroll
    for (int q = 0; q < NQ; ++q) sm[OFF_RED + warp * NQ + q] = acc[q];
  }
  __syncthreads();
  if (tid < NQ) {
    float s = 0.0f;
#pragma unroll
    for (int w = 0; w < NWARP; ++w) s += sm[OFF_RED + w * NQ + tid];
    out[b * NQ + tid] = s;
  }
}

} // namespace qc

extern "C" void kernel_launch(void* const* d_in, const int* in_sizes, int n_in,
                              void* d_out, int out_size) {
  const float* x    = (const float*)d_in[0];
  const float* prx  = (const float*)d_in[1];
  const float* pry  = (const float*)d_in[2];
  const float* prz  = (const float*)d_in[3];
  const float* pent = (const float*)d_in[4];
  float* out = (float*)d_out;
  const int batch = in_sizes[0] / qc::NQ;   // 128
  cudaFuncSetAttribute(qc::qc_kernel, cudaFuncAttributeMaxDynamicSharedMemorySize,
                       qc::SMEM_BYTES);
  qc::qc_kernel<<<batch, qc::NT, qc::SMEM_BYTES>>>(x, prx, pry, prz, pent, out);
}

// round 5
// speedup vs baseline: 1.3028x; 1.3028x over previous
#include <cuda_runtime.h>

namespace qc {

constexpr int NQ = 14;
constexpr int NL = 4;
constexpr int NS = 1 << NQ;       // 16384 amplitudes
constexpr int NT = 1024;          // one 16-amp group per thread
constexpr int NC = NQ - 1;
constexpr int NWARP = NT / 32;

// shared memory layout (float offsets). State is float2[NS] (re,im interleaved).
constexpr int OFF_U   = 2 * NS;                    // 56 gates * 8 floats
constexpr int OFF_ENC = OFF_U + NL * NQ * 8;       // 14 (c,s) pairs
constexpr int OFF_RED = OFF_ENC + 2 * NQ;          // 32 warps * 14 partials
constexpr int SMEM_FLOATS = OFF_RED + NWARP * NQ;
constexpr int SMEM_BYTES  = SMEM_FLOATS * 4;

// XOR swizzle on float2 element index: conflict-free (incl. 64-bit two-phase
// access) for all sweep bases used (S in {0,3,6,9,10}).
__device__ __forceinline__ int swz(int i) { return i ^ ((i >> 4) & 31); }

// Fused sweep over bits S..S+W-1:
//   1q gates (with prev layer's entangle-RZs pre-merged) on local bits G0..W-1,
//   then the bare CNOT chain (st=C0..W-2) folded into the store index (free).
// INIT: synthesize the RY-encoded product state instead of loading.
// MEAS: accumulate <Z_q> from registers instead of storing.
template<int S, int W, int G0, int C0, bool INIT, bool MEAS>
__device__ __forceinline__ void sweepFused(float2* __restrict__ st,
                                           const float* __restrict__ ul,   // 14*8 gate floats
                                           const float* __restrict__ enc,  // 14 (c,s)
                                           int tid, float* __restrict__ acc) {
  constexpr int M = 1 << W;
  static_assert((NS >> W) == NT, "one group per thread");
  const int base = ((tid >> S) << (S + W)) | (tid & ((1 << S) - 1));
  float vr[M], vi[M];

  if (INIT) {
    float T = 1.0f;
#pragma unroll
    for (int i = W; i < NQ; ++i)
      T *= ((base >> i) & 1) ? enc[2 * i + 1] : enc[2 * i];
#pragma unroll
    for (int o = 0; o < M; ++o) {
      float p = T;
#pragma unroll
      for (int i = 0; i < W; ++i)
        p *= ((o >> i) & 1) ? enc[2 * i + 1] : enc[2 * i];
      vr[o] = p; vi[o] = 0.0f;
    }
  } else {
#pragma unroll
    for (int o = 0; o < M; ++o) {
      const float2 v = st[swz(base | (o << S))];
      vr[o] = v.x; vi[o] = v.y;
    }
  }

  // 1q gates (distinct bits -> commuting)
#pragma unroll
  for (int j = G0; j < W; ++j) {
    const float* u = ul + (S + j) * 8;
    const float u0 = u[0], u1 = u[1], u2 = u[2], u3 = u[3];
    const float u4 = u[4], u5 = u[5], u6 = u[6], u7 = u[7];
#pragma unroll
    for (int o = 0; o < M; ++o) {
      if (o & (1 << j)) continue;
      const int o1 = o | (1 << j);
      const float ar = vr[o], ai = vi[o], br = vr[o1], bi = vi[o1];
      vr[o]  = u0*ar - u1*ai + u2*br - u3*bi;
      vi[o]  = u0*ai + u1*ar + u2*bi + u3*br;
      vr[o1] = u4*ar - u5*ai + u6*br - u7*bi;
      vi[o1] = u4*ai + u5*ar + u6*bi + u7*br;
    }
  }

  if (MEAS) {
    // CNOT chain permutation folded into the measured bit pattern.
    float tot = 0.0f, sb[W];
#pragma unroll
    for (int k = 0; k < W; ++k) sb[k] = 0.0f;
#pragma unroll
    for (int o = 0; o < M; ++o) {
      int po = o;
#pragma unroll
      for (int st2 = C0; st2 < W - 1; ++st2)
        if ((po >> st2) & 1) po ^= (2 << st2);
      const float pr = vr[o] * vr[o] + vi[o] * vi[o];
      tot += pr;
#pragma unroll
      for (int k = 0; k < W; ++k)
        if ((po >> k) & 1) sb[k] += pr;
    }
#pragma unroll
    for (int q = 0; q < NQ; ++q) {
      if (q >= S && q < S + W) acc[q] = tot - 2.0f * sb[q - S];
      else acc[q] = ((base >> q) & 1) ? -tot : tot;
    }
  } else {
    // store with the compile-time CNOT-chain permutation (ascending st order)
#pragma unroll
    for (int o = 0; o < M; ++o) {
      int po = o;
#pragma unroll
      for (int st2 = C0; st2 < W - 1; ++st2)
        if ((po >> st2) & 1) po ^= (2 << st2);
      st[swz(base | (po << S))] = make_float2(vr[o], vi[o]);
    }
  }
}

__global__ void __launch_bounds__(NT, 1)
qc_kernel(const float* __restrict__ x, const float* __restrict__ prx,
          const float* __restrict__ pry, const float* __restrict__ prz,
          const float* __restrict__ pent, float* __restrict__ out) {
  extern __shared__ float sm[];
  float2* st = reinterpret_cast<float2*>(sm);
  const float* enc = sm + OFF_ENC;
  const int tid = threadIdx.x;
  const int b = blockIdx.x;

  // ---- prologue: U = Rz*Ry*Rx, with PREVIOUS layer's entangle RZ merged in
  //      on the right (U' = U * RZ(ent[l-1][q-1]) for l>=1, q>=1). ----
  if (tid < NL * NQ) {
    const int l = tid / NQ, q = tid % NQ;
    float cx, sx, cy, sy, cz, sz;
    sincosf(0.5f * prx[tid], &sx, &cx);
    sincosf(0.5f * pry[tid], &sy, &cy);
    sincosf(0.5f * prz[tid], &sz, &cz);
    const float r00x =  cy*cx, r00y =  sy*sx;
    const float r01x = -sy*cx, r01y = -cy*sx;
    const float r10x =  sy*cx, r10y = -cy*sx;
    const float r11x =  cy*cx, r11y = -sy*sx;
    float u0 = r00x*cz + r00y*sz, u1 = r00y*cz - r00x*sz;
    float u2 = r01x*cz + r01y*sz, u3 = r01y*cz - r01x*sz;
    float u4 = r10x*cz - r10y*sz, u5 = r10x*sz + r10y*cz;
    float u6 = r11x*cz - r11y*sz, u7 = r11x*sz + r11y*cz;
    if (l >= 1 && q >= 1) {
      float c, s; sincosf(0.5f * pent[(l - 1) * NC + (q - 1)], &s, &c);
      float a;
      // column 0 *= e^{-i t/2} = (c,-s):  (x,y) -> (xc+ys, yc-xs)
      a = u0*c + u1*s;  u1 = u1*c - u0*s;  u0 = a;
      a = u4*c + u5*s;  u5 = u5*c - u4*s;  u4 = a;
      // column 1 *= e^{+i t/2} = (c, s):  (x,y) -> (xc-ys, yc+xs)
      a = u2*c - u3*s;  u3 = u3*c + u2*s;  u2 = a;
      a = u6*c - u7*s;  u7 = u7*c + u6*s;  u6 = a;
    }
    float* u = sm + OFF_U + tid * 8;
    u[0] = u0; u[1] = u1; u[2] = u2; u[3] = u3;
    u[4] = u4; u[5] = u5; u[6] = u6; u[7] = u7;
  }
  if (tid >= 64 && tid < 64 + NQ) {
    const int i = tid - 64;
    const float th = 0.5f * 3.14159265358979323846f * tanhf(x[b * NQ + i]);
    float c, s; sincosf(th, &s, &c);
    sm[OFF_ENC + 2*i] = c; sm[OFF_ENC + 2*i + 1] = s;
  }
  __syncthreads();

  // ---- layers: 5 fused sweeps; layer 0 synthesizes init; last sweep of the
  //      last layer measures from registers (no store, no extra pass). ----
  float acc[NQ];
  for (int l = 0; l < NL; ++l) {
    const float* ul = sm + OFF_U + l * NQ * 8;
    if (l == 0) {
      sweepFused<0, 4, 0, 0, true , false>(st, ul, enc, tid, acc);
    } else {
      __syncthreads();
      sweepFused<0, 4, 0, 0, false, false>(st, ul, enc, tid, acc);
    }
    __syncthreads(); sweepFused<3, 4, 1, 0, false, false>(st, ul, enc, tid, acc);
    __syncthreads(); sweepFused<6, 4, 1, 0, false, false>(st, ul, enc, tid, acc);
    __syncthreads(); sweepFused<9, 4, 1, 0, false, false>(st, ul, enc, tid, acc);
    __syncthreads();
    if (l < NL - 1) sweepFused<10, 4, 3, 2, false, false>(st, ul, enc, tid, acc);
    else            sweepFused<10, 4, 3, 2, false, true >(st, ul, enc, tid, acc);
  }

  // ---- reduction of per-thread <Z_q> partials ----
#pragma unroll
  for (int q = 0; q < NQ; ++q)
#pragma unroll
    for (int off = 16; off > 0; off >>= 1)
      acc[q] += __shfl_xor_sync(0xffffffffu, acc[q], off);
  const int warp = tid >> 5, lane = tid & 31;
  __syncthreads();   // state no longer needed; reuse smem region is distinct anyway
  if (lane == 0) {
#pragma unroll
    for (int q = 0; q < NQ; ++q) sm[OFF_RED + warp * NQ + q] = acc[q];
  }
  __syncthreads();
  if (tid < NQ) {
    float s = 0.0f;
#pragma unroll
    for (int w = 0; w < NWARP; ++w) s += sm[OFF_RED + w * NQ + tid];
    out[b * NQ + tid] = s;
  }
}

} // namespace qc

extern "C" void kernel_launch(void* const* d_in, const int* in_sizes, int n_in,
                              void* d_out, int out_size) {
  const float* x    = (const float*)d_in[0];
  const float* prx  = (const float*)d_in[1];
  const float* pry  = (const float*)d_in[2];
  const float* prz  = (const float*)d_in[3];
  const float* pent = (const float*)d_in[4];
  float* out = (float*)d_out;
  const int batch = in_sizes[0] / qc::NQ;   // 128
  cudaFuncSetAttribute(qc::qc_kernel, cudaFuncAttributeMaxDynamicSharedMemorySize,
                       qc::SMEM_BYTES);
  qc::qc_kernel<<<batch, qc::NT, qc::SMEM_BYTES>>>(x, prx, pry, prz, pent, out);
}

// round 6
// speedup vs baseline: 1.6608x; 1.2748x over previous
#include <cuda_runtime.h>

namespace qc {

constexpr int NQ = 14;
constexpr int NL = 4;
constexpr int NS = 1 << NQ;       // 16384 amplitudes
constexpr int NT = 1024;          // one 16-amp group per thread
constexpr int NC = NQ - 1;
constexpr int NWARP = NT / 32;
constexpr int NGL = NL - 1;       // gate layers stored (layers 1..3)

// shared memory layout (float offsets). State is float2[NS].
constexpr int OFF_U   = 2 * NS;                    // 42 gates * 8 floats
constexpr int OFF_V   = OFF_U + NGL * NQ * 8;      // 14 qubits * 2 cplx (layer-0 product vectors)
constexpr int OFF_RED = OFF_V + NQ * 4;
constexpr int SMEM_FLOATS = OFF_RED + NWARP * NQ;
constexpr int SMEM_BYTES  = SMEM_FLOATS * 4;

// XOR swizzle on float2 index: conflict-free for S in {0,3,6,9,10}
__device__ __forceinline__ int swz(int i) { return i ^ ((i >> 4) & 31); }

__device__ __forceinline__ float2 cmul(float2 a, float2 b) {
  return make_float2(a.x * b.x - a.y * b.y, a.x * b.y + a.y * b.x);
}

// Fused sweep over bits S..S+W-1:
//   1q gates (prev layer's entangle-RZs pre-merged) on local bits G0..W-1,
//   then the bare CNOT chain (st=C0..W-2) folded into the store index.
// SYNTH: synthesize the post-layer-0 state (product state pushed through the
//        layer-0 prefix-XOR CNOT permutation) instead of loading (S==0 only).
// MEAS:  accumulate <Z_q> from registers instead of storing.
template<int S, int W, int G0, int C0, bool SYNTH, bool MEAS>
__device__ __forceinline__ void sweepFused(float2* __restrict__ st,
                                           const float* __restrict__ ul,   // this layer's 14*8
                                           const float2* __restrict__ vv,  // 14*2 product vectors
                                           int tid, float* __restrict__ acc) {
  constexpr int M = 1 << W;
  static_assert((NS >> W) == NT, "one group per thread");
  const int base = ((tid >> S) << (S + W)) | (tid & ((1 << S) - 1));
  float vr[M], vi[M];

  if (SYNTH) {
    static_assert(!SYNTH || (S == 0 && W == 4), "synth assumes S=0,W=4");
    // amp(y) = prod_j v_j[x_j], x_j = y_j ^ y_{j-1};  y = (tid<<4) | o
    const int t = tid;
    float2 P = vv[5 * 2 + (((t >> 1) ^ t) & 1)];          // x5 = t1^t0
#pragma unroll
    for (int j = 6; j < NQ; ++j)
      P = cmul(P, vv[j * 2 + (((t >> (j - 4)) ^ (t >> (j - 5))) & 1)]);
    const int t0 = t & 1;
    float2 Pv[2];                                          // x4 = t0 ^ o3
    Pv[0] = cmul(P, vv[4 * 2 + t0]);
    Pv[1] = cmul(P, vv[4 * 2 + (t0 ^ 1)]);
    float2 g[8];                                           // [o0 + 2*o1 + 4*o2]
#pragma unroll
    for (int o0 = 0; o0 < 2; ++o0)
#pragma unroll
      for (int o1 = 0; o1 < 2; ++o1) {
        const float2 h = cmul(vv[0 * 2 + o0], vv[1 * 2 + (o1 ^ o0)]);
#pragma unroll
        for (int o2 = 0; o2 < 2; ++o2)
          g[o0 + 2 * o1 + 4 * o2] = cmul(h, vv[2 * 2 + (o2 ^ o1)]);
      }
    float2 w[4];                                           // [o2 + 2*o3]
#pragma unroll
    for (int o2 = 0; o2 < 2; ++o2)
#pragma unroll
      for (int o3 = 0; o3 < 2; ++o3)
        w[o2 + 2 * o3] = cmul(vv[3 * 2 + (o3 ^ o2)], Pv[o3]);
#pragma unroll
    for (int o = 0; o < M; ++o) {
      const float2 a = cmul(g[o & 7], w[(o >> 2) & 3]);
      vr[o] = a.x; vi[o] = a.y;
    }
  } else {
#pragma unroll
    for (int o = 0; o < M; ++o) {
      const float2 v = st[swz(base | (o << S))];
      vr[o] = v.x; vi[o] = v.y;
    }
  }

  // 1q gates (distinct bits -> commuting)
#pragma unroll
  for (int j = G0; j < W; ++j) {
    const float* u = ul + (S + j) * 8;
    const float u0 = u[0], u1 = u[1], u2 = u[2], u3 = u[3];
    const float u4 = u[4], u5 = u[5], u6 = u[6], u7 = u[7];
#pragma unroll
    for (int o = 0; o < M; ++o) {
      if (o & (1 << j)) continue;
      const int o1 = o | (1 << j);
      const float ar = vr[o], ai = vi[o], br = vr[o1], bi = vi[o1];
      vr[o]  = u0*ar - u1*ai + u2*br - u3*bi;
      vi[o]  = u0*ai + u1*ar + u2*bi + u3*br;
      vr[o1] = u4*ar - u5*ai + u6*br - u7*bi;
      vi[o1] = u4*ai + u5*ar + u6*bi + u7*br;
    }
  }

  if (MEAS) {
    float tot = 0.0f, sb[W];
#pragma unroll
    for (int k = 0; k < W; ++k) sb[k] = 0.0f;
#pragma unroll
    for (int o = 0; o < M; ++o) {
      int po = o;
#pragma unroll
      for (int st2 = C0; st2 < W - 1; ++st2)
        if ((po >> st2) & 1) po ^= (2 << st2);
      const float pr = vr[o] * vr[o] + vi[o] * vi[o];
      tot += pr;
#pragma unroll
      for (int k = 0; k < W; ++k)
        if ((po >> k) & 1) sb[k] += pr;
    }
#pragma unroll
    for (int q = 0; q < NQ; ++q) {
      if (q >= S && q < S + W) acc[q] = tot - 2.0f * sb[q - S];
      else acc[q] = ((base >> q) & 1) ? -tot : tot;
    }
  } else {
#pragma unroll
    for (int o = 0; o < M; ++o) {
      int po = o;
#pragma unroll
      for (int st2 = C0; st2 < W - 1; ++st2)
        if ((po >> st2) & 1) po ^= (2 << st2);
      st[swz(base | (po << S))] = make_float2(vr[o], vi[o]);
    }
  }
}

__global__ void __launch_bounds__(NT, 1)
qc_kernel(const float* __restrict__ x, const float* __restrict__ prx,
          const float* __restrict__ pry, const float* __restrict__ prz,
          const float* __restrict__ pent, float* __restrict__ out) {
  extern __shared__ float sm[];
  float2* st = reinterpret_cast<float2*>(sm);
  float2* vv = reinterpret_cast<float2*>(sm + OFF_V);
  const int tid = threadIdx.x;
  const int b = blockIdx.x;

  // ---- prologue: gates for layers 1..3 (U' = Rz*Ry*Rx * RZ_ent[l-1]) ----
  if (tid < NGL * NQ) {
    const int q = tid % NQ;
    const int idx = tid + NQ;   // (l,q) with l = tid/NQ + 1
    float cx, sx, cy, sy, cz, sz;
    sincosf(0.5f * prx[idx], &sx, &cx);
    sincosf(0.5f * pry[idx], &sy, &cy);
    sincosf(0.5f * prz[idx], &sz, &cz);
    const float r00x =  cy*cx, r00y =  sy*sx;
    const float r01x = -sy*cx, r01y = -cy*sx;
    const float r10x =  sy*cx, r10y = -cy*sx;
    const float r11x =  cy*cx, r11y = -sy*sx;
    float u0 = r00x*cz + r00y*sz, u1 = r00y*cz - r00x*sz;
    float u2 = r01x*cz + r01y*sz, u3 = r01y*cz - r01x*sz;
    float u4 = r10x*cz - r10y*sz, u5 = r10x*sz + r10y*cz;
    float u6 = r11x*cz - r11y*sz, u7 = r11x*sz + r11y*cz;
    if (q >= 1) {
      float c, s; sincosf(0.5f * pent[(tid / NQ) * NC + (q - 1)], &s, &c);
      float a;
      a = u0*c + u1*s;  u1 = u1*c - u0*s;  u0 = a;   // col 0 *= e^{-i t/2}
      a = u4*c + u5*s;  u5 = u5*c - u4*s;  u4 = a;
      a = u2*c - u3*s;  u3 = u3*c + u2*s;  u2 = a;   // col 1 *= e^{+i t/2}
      a = u6*c - u7*s;  u7 = u7*c + u6*s;  u6 = a;
    }
    float* u = sm + OFF_U + tid * 8;
    u[0] = u0; u[1] = u1; u[2] = u2; u[3] = u3;
    u[4] = u4; u[5] = u5; u[6] = u6; u[7] = u7;
  }
  // ---- layer-0 gates folded into product vectors: v_j = U_0(j) * (c_j, s_j)^T ----
  if (tid >= 64 && tid < 64 + NQ) {
    const int j = tid - 64;
    float cx, sx, cy, sy, cz, sz;
    sincosf(0.5f * prx[j], &sx, &cx);
    sincosf(0.5f * pry[j], &sy, &cy);
    sincosf(0.5f * prz[j], &sz, &cz);
    const float r00x =  cy*cx, r00y =  sy*sx;
    const float r01x = -sy*cx, r01y = -cy*sx;
    const float r10x =  sy*cx, r10y = -cy*sx;
    const float r11x =  cy*cx, r11y = -sy*sx;
    const float u0 = r00x*cz + r00y*sz, u1 = r00y*cz - r00x*sz;
    const float u2 = r01x*cz + r01y*sz, u3 = r01y*cz - r01x*sz;
    const float u4 = r10x*cz - r10y*sz, u5 = r10x*sz + r10y*cz;
    const float u6 = r11x*cz - r11y*sz, u7 = r11x*sz + r11y*cz;
    const float th = 0.5f * 3.14159265358979323846f * tanhf(x[b * NQ + j]);
    float c, s; sincosf(th, &s, &c);
    vv[j * 2 + 0] = make_float2(u0 * c + u2 * s, u1 * c + u3 * s);
    vv[j * 2 + 1] = make_float2(u4 * c + u6 * s, u5 * c + u7 * s);
  }
  __syncthreads();

  float acc[NQ];
  // ---- layer 1: synth pass (layer 0 + layer-1 S=0 gates), then 4 sweeps ----
  {
    const float* ul = sm + OFF_U;   // layer 1 gates
    sweepFused<0, 4, 0, 0, true , false>(st, ul, vv, tid, acc);
    __syncthreads(); sweepFused<3,  4, 1, 0, false, false>(st, ul, vv, tid, acc);
    __syncthreads(); sweepFused<6,  4, 1, 0, false, false>(st, ul, vv, tid, acc);
    __syncthreads(); sweepFused<9,  4, 1, 0, false, false>(st, ul, vv, tid, acc);
    __syncthreads(); sweepFused<10, 4, 3, 2, false, false>(st, ul, vv, tid, acc);
  }
  // ---- layers 2..3: 5 sweeps each; very last sweep measures from registers ----
  for (int l = 2; l < NL; ++l) {
    const float* ul = sm + OFF_U + (l - 1) * NQ * 8;
    __syncthreads(); sweepFused<0, 4, 0, 0, false, false>(st, ul, vv, tid, acc);
    __syncthreads(); sweepFused<3, 4, 1, 0, false, false>(st, ul, vv, tid, acc);
    __syncthreads(); sweepFused<6, 4, 1, 0, false, false>(st, ul, vv, tid, acc);
    __syncthreads(); sweepFused<9, 4, 1, 0, false, false>(st, ul, vv, tid, acc);
    __syncthreads();
    if (l < NL - 1) sweepFused<10, 4, 3, 2, false, false>(st, ul, vv, tid, acc);
    else            sweepFused<10, 4, 3, 2, false, true >(st, ul, vv, tid, acc);
  }

  // ---- reduction of per-thread <Z_q> partials ----
#pragma unroll
  for (int q = 0; q < NQ; ++q)
#pragma unroll
    for (int off = 16; off > 0; off >>= 1)
      acc[q] += __shfl_xor_sync(0xffffffffu, acc[q], off);
  const int warp = tid >> 5, lane = tid & 31;
  __syncthreads();
  if (lane == 0) {
#pragma unroll
    for (int q = 0; q < NQ; ++q) sm[OFF_RED + warp * NQ + q] = acc[q];
  }
  __syncthreads();
  if (tid < NQ) {
    float s = 0.0f;
#pragma unroll
    for (int w = 0; w < NWARP; ++w) s += sm[OFF_RED + w * NQ + tid];
    out[b * NQ + tid] = s;
  }
}

} // namespace qc

extern "C" void kernel_launch(void* const* d_in, const int* in_sizes, int n_in,
                              void* d_out, int out_size) {
  const float* x    = (const float*)d_in[0];
  const float* prx  = (const float*)d_in[1];
  const float* pry  = (const float*)d_in[2];
  const float* prz  = (const float*)d_in[3];
  const float* pent = (const float*)d_in[4];
  float* out = (float*)d_out;
  const int batch = in_sizes[0] / qc::NQ;   // 128
  cudaFuncSetAttribute(qc::qc_kernel, cudaFuncAttributeMaxDynamicSharedMemorySize,
                       qc::SMEM_BYTES);
  qc::qc_kernel<<<batch, qc::NT, qc::SMEM_BYTES>>>(x, prx, pry, prz, pent, out);
}

// round 7
// speedup vs baseline: 1.7119x; 1.0308x over previous
#include <cuda_runtime.h>

namespace qc {

constexpr int NQ = 14;
constexpr int NL = 4;
constexpr int NS = 1 << NQ;       // 16384 amplitudes
constexpr int NT = 512;           // one 32-amp group per thread (W=5)
constexpr int NC = NQ - 1;
constexpr int NWARP = NT / 32;    // 16
constexpr int NGL = NL - 1;       // gate layers stored (layers 1..3)
constexpr int W = 5;
constexpr int M = 1 << W;         // 32 amps per group

// shared memory layout (float offsets). State is float2[NS].
constexpr int OFF_U   = 2 * NS;                    // 42 gates * 8 floats
constexpr int OFF_V   = OFF_U + NGL * NQ * 8;      // 14 qubits * 2 cplx
constexpr int OFF_RED = OFF_V + NQ * 4;
constexpr int SMEM_FLOATS = OFF_RED + NWARP * NQ;
constexpr int SMEM_BYTES  = SMEM_FLOATS * 4;

// XOR swizzle on float2 index: conflict-free (64-bit, per-half-warp) for all
// W=5 sweep bases S in {0,4,8,9}, loads and CNOT-folded stores alike.
__device__ __forceinline__ int swz(int i) { return i ^ ((i >> 5) & 31); }

__device__ __forceinline__ float2 cmul(float2 a, float2 b) {
  return make_float2(a.x * b.x - a.y * b.y, a.x * b.y + a.y * b.x);
}

// Fused W=5 sweep over bits S..S+4:
//   1q gates (prev layer's entangle-RZs pre-merged) on local bits G0..4,
//   then bare CNOT chain (st=C0..3) folded into the store index (free).
// SYNTH (S==0): synthesize post-layer-0 state (product state through the
//   layer-0 prefix-XOR CNOT permutation) instead of loading.
// MEAS: accumulate <Z_q> from registers instead of storing.
template<int S, int G0, int C0, bool SYNTH, bool MEAS>
__device__ __forceinline__ void sweep5(float2* __restrict__ st,
                                       const float* __restrict__ ul,   // this layer's 14*8
                                       const float2* __restrict__ vv,  // 14*2 product vectors
                                       int tid, float* __restrict__ acc) {
  static_assert((NS >> W) == NT, "one group per thread");
  const int base = ((tid >> S) << (S + W)) | (tid & ((1 << S) - 1));
  float vr[M], vi[M];

  if (SYNTH) {
    static_assert(!SYNTH || S == 0, "synth assumes S=0");
    // amp(y) = prod_j v_j[x_j], x_j = y_j ^ y_{j-1};  y = (tid<<5) | o
    const int t = tid;
    float2 P = vv[6 * 2 + (((t >> 1) ^ t) & 1)];           // x6 = t1^t0
#pragma unroll
    for (int j = 7; j < NQ; ++j)
      P = cmul(P, vv[j * 2 + (((t >> (j - 5)) ^ (t >> (j - 6))) & 1)]);
    const int t0 = t & 1;
    float2 Pv5[2];                                          // x5 = t0 ^ o4
    Pv5[0] = cmul(P, vv[5 * 2 + t0]);
    Pv5[1] = cmul(P, vv[5 * 2 + (t0 ^ 1)]);
    float2 a34[4];                                          // [o3 + 2*o4]
#pragma unroll
    for (int o3 = 0; o3 < 2; ++o3)
#pragma unroll
      for (int o4 = 0; o4 < 2; ++o4)
        a34[o3 + 2 * o4] = cmul(vv[4 * 2 + (o4 ^ o3)], Pv5[o4]);
    float2 w[8];                                            // [o2 + 2*o3 + 4*o4]
#pragma unroll
    for (int o2 = 0; o2 < 2; ++o2)
#pragma unroll
      for (int o3 = 0; o3 < 2; ++o3)
#pragma unroll
        for (int o4 = 0; o4 < 2; ++o4)
          w[o2 + 2 * o3 + 4 * o4] = cmul(vv[3 * 2 + (o3 ^ o2)], a34[o3 + 2 * o4]);
    float2 g[8];                                            // [o0 + 2*o1 + 4*o2]
#pragma unroll
    for (int o0 = 0; o0 < 2; ++o0)
#pragma unroll
      for (int o1 = 0; o1 < 2; ++o1) {
        const float2 h = cmul(vv[0 * 2 + o0], vv[1 * 2 + (o1 ^ o0)]);
#pragma unroll
        for (int o2 = 0; o2 < 2; ++o2)
          g[o0 + 2 * o1 + 4 * o2] = cmul(h, vv[2 * 2 + (o2 ^ o1)]);
      }
#pragma unroll
    for (int o = 0; o < M; ++o) {
      const float2 a = cmul(g[o & 7], w[(o >> 2) & 7]);
      vr[o] = a.x; vi[o] = a.y;
    }
  } else {
#pragma unroll
    for (int o = 0; o < M; ++o) {
      const float2 v = st[swz(base | (o << S))];
      vr[o] = v.x; vi[o] = v.y;
    }
  }

  // 1q gates (distinct bits -> commuting)
#pragma unroll
  for (int j = G0; j < W; ++j) {
    const float* u = ul + (S + j) * 8;
    const float u0 = u[0], u1 = u[1], u2 = u[2], u3 = u[3];
    const float u4 = u[4], u5 = u[5], u6 = u[6], u7 = u[7];
#pragma unroll
    for (int o = 0; o < M; ++o) {
      if (o & (1 << j)) continue;
      const int o1 = o | (1 << j);
      const float ar = vr[o], ai = vi[o], br = vr[o1], bi = vi[o1];
      vr[o]  = u0*ar - u1*ai + u2*br - u3*bi;
      vi[o]  = u0*ai + u1*ar + u2*bi + u3*br;
      vr[o1] = u4*ar - u5*ai + u6*br - u7*bi;
      vi[o1] = u4*ai + u5*ar + u6*bi + u7*br;
    }
  }

  if (MEAS) {
    float tot = 0.0f, sb[W];
#pragma unroll
    for (int k = 0; k < W; ++k) sb[k] = 0.0f;
#pragma unroll
    for (int o = 0; o < M; ++o) {
      int po = o;
#pragma unroll
      for (int st2 = C0; st2 < W - 1; ++st2)
        if ((po >> st2) & 1) po ^= (2 << st2);
      const float pr = vr[o] * vr[o] + vi[o] * vi[o];
      tot += pr;
#pragma unroll
      for (int k = 0; k < W; ++k)
        if ((po >> k) & 1) sb[k] += pr;
    }
#pragma unroll
    for (int q = 0; q < NQ; ++q) {
      if (q >= S && q < S + W) acc[q] = tot - 2.0f * sb[q - S];
      else acc[q] = ((base >> q) & 1) ? -tot : tot;
    }
  } else {
#pragma unroll
    for (int o = 0; o < M; ++o) {
      int po = o;
#pragma unroll
      for (int st2 = C0; st2 < W - 1; ++st2)
        if ((po >> st2) & 1) po ^= (2 << st2);
      st[swz(base | (po << S))] = make_float2(vr[o], vi[o]);
    }
  }
}

__global__ void __launch_bounds__(NT, 1)
qc_kernel(const float* __restrict__ x, const float* __restrict__ prx,
          const float* __restrict__ pry, const float* __restrict__ prz,
          const float* __restrict__ pent, float* __restrict__ out) {
  extern __shared__ float sm[];
  float2* st = reinterpret_cast<float2*>(sm);
  float2* vv = reinterpret_cast<float2*>(sm + OFF_V);
  const int tid = threadIdx.x;
  const int b = blockIdx.x;

  // ---- prologue: gates for layers 1..3 (U' = Rz*Ry*Rx * RZ_ent[l-1]) ----
  if (tid < NGL * NQ) {
    const int q = tid % NQ;
    const int idx = tid + NQ;   // (l,q) with l = tid/NQ + 1
    float cx, sx, cy, sy, cz, sz;
    sincosf(0.5f * prx[idx], &sx, &cx);
    sincosf(0.5f * pry[idx], &sy, &cy);
    sincosf(0.5f * prz[idx], &sz, &cz);
    const float r00x =  cy*cx, r00y =  sy*sx;
    const float r01x = -sy*cx, r01y = -cy*sx;
    const float r10x =  sy*cx, r10y = -cy*sx;
    const float r11x =  cy*cx, r11y = -sy*sx;
    float u0 = r00x*cz + r00y*sz, u1 = r00y*cz - r00x*sz;
    float u2 = r01x*cz + r01y*sz, u3 = r01y*cz - r01x*sz;
    float u4 = r10x*cz - r10y*sz, u5 = r10x*sz + r10y*cz;
    float u6 = r11x*cz - r11y*sz, u7 = r11x*sz + r11y*cz;
    if (q >= 1) {
      float c, s; sincosf(0.5f * pent[(tid / NQ) * NC + (q - 1)], &s, &c);
      float a;
      a = u0*c + u1*s;  u1 = u1*c - u0*s;  u0 = a;   // col 0 *= e^{-i t/2}
      a = u4*c + u5*s;  u5 = u5*c - u4*s;  u4 = a;
      a = u2*c - u3*s;  u3 = u3*c + u2*s;  u2 = a;   // col 1 *= e^{+i t/2}
      a = u6*c - u7*s;  u7 = u7*c + u6*s;  u6 = a;
    }
    float* u = sm + OFF_U + tid * 8;
    u[0] = u0; u[1] = u1; u[2] = u2; u[3] = u3;
    u[4] = u4; u[5] = u5; u[6] = u6; u[7] = u7;
  }
  // ---- layer-0 gates folded into product vectors: v_j = U_0(j) * (c_j, s_j)^T ----
  if (tid >= 64 && tid < 64 + NQ) {
    const int j = tid - 64;
    float cx, sx, cy, sy, cz, sz;
    sincosf(0.5f * prx[j], &sx, &cx);
    sincosf(0.5f * pry[j], &sy, &cy);
    sincosf(0.5f * prz[j], &sz, &cz);
    const float r00x =  cy*cx, r00y =  sy*sx;
    const float r01x = -sy*cx, r01y = -cy*sx;
    const float r10x =  sy*cx, r10y = -cy*sx;
    const float r11x =  cy*cx, r11y = -sy*sx;
    const float u0 = r00x*cz + r00y*sz, u1 = r00y*cz - r00x*sz;
    const float u2 = r01x*cz + r01y*sz, u3 = r01y*cz - r01x*sz;
    const float u4 = r10x*cz - r10y*sz, u5 = r10x*sz + r10y*cz;
    const float u6 = r11x*cz - r11y*sz, u7 = r11x*sz + r11y*cz;
    const float th = 0.5f * 3.14159265358979323846f * tanhf(x[b * NQ + j]);
    float c, s; sincosf(th, &s, &c);
    vv[j * 2 + 0] = make_float2(u0 * c + u2 * s, u1 * c + u3 * s);
    vv[j * 2 + 1] = make_float2(u4 * c + u6 * s, u5 * c + u7 * s);
  }
  __syncthreads();

  float acc[NQ];
  // ---- layer 1: synth pass (layer 0 + layer-1 S=0 block), then 3 sweeps ----
  {
    const float* ul = sm + OFF_U;   // layer 1 gates
    sweep5<0, 0, 0, true , false>(st, ul, vv, tid, acc);
    __syncthreads(); sweep5<4, 1, 0, false, false>(st, ul, vv, tid, acc);
    __syncthreads(); sweep5<8, 1, 0, false, false>(st, ul, vv, tid, acc);
    __syncthreads(); sweep5<9, 4, 3, false, false>(st, ul, vv, tid, acc);
  }
  // ---- layers 2..3: 4 sweeps each; very last sweep measures from registers ----
  for (int l = 2; l < NL; ++l) {
    const float* ul = sm + OFF_U + (l - 1) * NQ * 8;
    __syncthreads(); sweep5<0, 0, 0, false, false>(st, ul, vv, tid, acc);
    __syncthreads(); sweep5<4, 1, 0, false, false>(st, ul, vv, tid, acc);
    __syncthreads(); sweep5<8, 1, 0, false, false>(st, ul, vv, tid, acc);
    __syncthreads();
    if (l < NL - 1) sweep5<9, 4, 3, false, false>(st, ul, vv, tid, acc);
    else            sweep5<9, 4, 3, false, true >(st, ul, vv, tid, acc);
  }

  // ---- reduction of per-thread <Z_q> partials ----
#pragma unroll
  for (int q = 0; q < NQ; ++q)
#pragma unroll
    for (int off = 16; off > 0; off >>= 1)
      acc[q] += __shfl_xor_sync(0xffffffffu, acc[q], off);
  const int warp = tid >> 5, lane = tid & 31;
  __syncthreads();
  if (lane == 0) {
#pragma unroll
    for (int q = 0; q < NQ; ++q) sm[OFF_RED + warp * NQ + q] = acc[q];
  }
  __syncthreads();
  if (tid < NQ) {
    float s = 0.0f;
#pragma unroll
    for (int w = 0; w < NWARP; ++w) s += sm[OFF_RED + w * NQ + tid];
    out[b * NQ + tid] = s;
  }
}

} // namespace qc

extern "C" void kernel_launch(void* const* d_in, const int* in_sizes, int n_in,
                              void* d_out, int out_size) {
  const float* x    = (const float*)d_in[0];
  const float* prx  = (const float*)d_in[1];
  const float* pry  = (const float*)d_in[2];
  const float* prz  = (const float*)d_in[3];
  const float* pent = (const float*)d_in[4];
  float* out = (float*)d_out;
  const int batch = in_sizes[0] / qc::NQ;   // 128
  cudaFuncSetAttribute(qc::qc_kernel, cudaFuncAttributeMaxDynamicSharedMemorySize,
                       qc::SMEM_BYTES);
  qc::qc_kernel<<<batch, qc::NT, qc::SMEM_BYTES>>>(x, prx, pry, prz, pent, out);
}